// round 10
// baseline (speedup 1.0000x reference)
#include <cuda_runtime.h>
#include <cuda_fp16.h>
#include <cuda_bf16.h>
#include <cstdint>

#define BB 4
#define TE 512
#define TD 256
#define HE 128
#define HD 256
#define TT 4
#define FP 64      // features 0..63  -> f32 Pade path (FMA pipe + RCP)
#define FM 64      // features 64..127 -> f16x2 MUFU tanh path

// ---- scratch (device globals; no allocation allowed) ----
__device__ float  g_Wsf[BB * TE * HE];      // enc @ W_a  f32  (4 MB)
__device__ __half g_Wsh[BB * TE * HE];      // enc @ W_a  half (1 MB)
__device__ float  g_Uhf[BB * TD * HE];      // dec @ U_a  f32
__device__ __half g_Uhh[BB * TD * HE];      // dec @ U_a  half
__device__ float  g_scores[BB * TD * TE];   // raw scores [B,TD,TE] (2 MB)

__device__ __forceinline__ __half2 tanh2_f16(__half2 x) {
    uint32_t xi = *reinterpret_cast<uint32_t*>(&x);
    uint32_t yi;
    asm("tanh.approx.f16x2 %0, %1;" : "=r"(yi) : "r"(xi));
    return *reinterpret_cast<__half2*>(&yi);
}
__device__ __forceinline__ __half2 u2h(uint32_t v) {
    return *reinterpret_cast<__half2*>(&v);
}
__device__ __forceinline__ float fast_rcp(float x) {
    float r;
    asm("rcp.approx.ftz.f32 %0, %1;" : "=f"(r) : "f"(x));
    return r;
}
// contribution v * tanh_pade(x) added to acc.
// tanh(x) ~= x*(10395 + 1260 t + 21 t^2) / (10395 + 4725 t + 210 t^2 + t^3), t=x^2
// max abs err ~4.5e-4 at |x|=4.4 (clamped), ~1e-5 mid-range.
__device__ __forceinline__ float pade_acc(float x, float v, float acc) {
    x = fminf(fmaxf(x, -4.4f), 4.4f);
    float t2 = x * x;
    float n = fmaf(t2, 21.0f, 1260.0f);
    n = fmaf(t2, n, 10395.0f);
    float d = t2 + 210.0f;
    d = fmaf(t2, d, 4725.0f);
    d = fmaf(t2, d, 10395.0f);
    float r = fast_rcp(d);
    float vx = v * x;
    return fmaf(vx * n, r, acc);
}

// ================= Prep kernel: Uh = dec@U  and  Ws = enc@W (f32 + half) ====
__global__ __launch_bounds__(128) void prep_kernel(
    const float* __restrict__ dec, const float* __restrict__ U,
    const float* __restrict__ enc, const float* __restrict__ W)
{
    __shared__ float sbuf[1024];                 // 4 KB
    int tid = threadIdx.x;

    if (blockIdx.x < 256) {
        // ---- Uh: rows = B*TD, 4 per block ----
        int blk = blockIdx.x;
        int b  = blk >> 6;
        int t0 = (blk & 63) * 4;
        const float4* drow = reinterpret_cast<const float4*>(dec + ((size_t)b * TD + t0) * HD);
        float4* sb4 = reinterpret_cast<float4*>(sbuf);
#pragma unroll
        for (int i = 0; i < 2; i++) sb4[tid + 128 * i] = drow[tid + 128 * i];
        __syncthreads();

        float a0 = 0.f, a1 = 0.f, a2 = 0.f, a3 = 0.f;
#pragma unroll 4
        for (int d = 0; d < HD; d += 4) {
            float u0 = U[(d + 0) * HE + tid];
            float u1 = U[(d + 1) * HE + tid];
            float u2 = U[(d + 2) * HE + tid];
            float u3 = U[(d + 3) * HE + tid];
#pragma unroll
            for (int j = 0; j < 4; j++) {
                float uj = (j == 0) ? u0 : (j == 1) ? u1 : (j == 2) ? u2 : u3;
                a0 = fmaf(sbuf[0 * HD + d + j], uj, a0);
                a1 = fmaf(sbuf[1 * HD + d + j], uj, a1);
                a2 = fmaf(sbuf[2 * HD + d + j], uj, a2);
                a3 = fmaf(sbuf[3 * HD + d + j], uj, a3);
            }
        }
        size_t base = ((size_t)(b * TD + t0)) * HE + tid;
        g_Uhf[base + 0 * HE] = a0;  g_Uhh[base + 0 * HE] = __float2half_rn(a0);
        g_Uhf[base + 1 * HE] = a1;  g_Uhh[base + 1 * HE] = __float2half_rn(a1);
        g_Uhf[base + 2 * HE] = a2;  g_Uhh[base + 2 * HE] = __float2half_rn(a2);
        g_Uhf[base + 3 * HE] = a3;  g_Uhh[base + 3 * HE] = __float2half_rn(a3);
    } else {
        // ---- Ws: rows = B*TE, 8 per block ----
        int blk = blockIdx.x - 256;
        int b  = blk >> 6;
        int s0 = (blk & 63) * 8;
        const float4* erow = reinterpret_cast<const float4*>(enc + ((size_t)b * TE + s0) * HE);
        float4* sb4 = reinterpret_cast<float4*>(sbuf);
#pragma unroll
        for (int i = 0; i < 2; i++) sb4[tid + 128 * i] = erow[tid + 128 * i];
        __syncthreads();

        float acc[8];
#pragma unroll
        for (int r = 0; r < 8; r++) acc[r] = 0.f;
#pragma unroll 2
        for (int k = 0; k < HE; k += 4) {
            float w0 = W[(k + 0) * HE + tid];
            float w1 = W[(k + 1) * HE + tid];
            float w2 = W[(k + 2) * HE + tid];
            float w3 = W[(k + 3) * HE + tid];
#pragma unroll
            for (int r = 0; r < 8; r++) {
                float aa = acc[r];
                aa = fmaf(sbuf[r * HE + k + 0], w0, aa);
                aa = fmaf(sbuf[r * HE + k + 1], w1, aa);
                aa = fmaf(sbuf[r * HE + k + 2], w2, aa);
                aa = fmaf(sbuf[r * HE + k + 3], w3, aa);
                acc[r] = aa;
            }
        }
        size_t base = ((size_t)(b * TE + s0)) * HE + tid;
#pragma unroll
        for (int r = 0; r < 8; r++) {
            g_Wsf[base + (size_t)r * HE] = acc[r];
            g_Wsh[base + (size_t)r * HE] = __float2half_rn(acc[r]);
        }
    }
}

// ================= Score kernel: hybrid FMA-Pade / MUFU-tanh ==============
// 1024 CTAs: blk = ((b*4 + chunk)*64 + ttile); 128 threads, thread = one s.
__global__ __launch_bounds__(128) void score_kernel(const float* __restrict__ Va)
{
    __shared__ float  s_uhf[TT * FP];            // 1 KB  (features 0..63, f32)
    __shared__ __half s_uhh[TT * FM];            // 0.5 KB (features 64..127)
    __shared__ float  s_vf[FP];                  // 256 B
    __shared__ __half s_vh[FM];                  // 128 B

    int blk   = blockIdx.x;
    int ttile = blk & 63;
    int chunk = (blk >> 6) & 3;
    int b     = blk >> 8;
    int t0    = ttile * TT;
    int tid   = threadIdx.x;                     // 0..127
    int s     = chunk * 128 + tid;

    // stage Uh tiles + V
    for (int i = tid; i < TT * FP; i += 128) {
        int t = i >> 6, f = i & 63;
        s_uhf[t * FP + f] = g_Uhf[((size_t)(b * TD + t0 + t)) * HE + f];
        s_uhh[t * FM + f] = g_Uhh[((size_t)(b * TD + t0 + t)) * HE + FP + f];
    }
    if (tid < FP) s_vf[tid] = Va[tid];
    else          s_vh[tid - FP] = __float2half_rn(Va[FP + (tid - FP)]);
    __syncthreads();

    const float4* uhf4 = reinterpret_cast<const float4*>(s_uhf);
    const uint4*  uhh4 = reinterpret_cast<const uint4*>(s_uhh);
    const float4* vf4  = reinterpret_cast<const float4*>(s_vf);
    const uint4*  vh4  = reinterpret_cast<const uint4*>(s_vh);
    const float4* wf4  = reinterpret_cast<const float4*>(
        g_Wsf + ((size_t)b * TE + s) * HE);          // 16 float4 (f 0..63)
    const uint4*  wh4  = reinterpret_cast<const uint4*>(
        g_Wsh + ((size_t)b * TE + s) * HE + FP);     // 8 uint4 (f 64..127)

    // ---- Pade path (f32, FMA pipe + MUFU RCP), features 0..63 ----
    float accP0[TT], accP1[TT];
#pragma unroll
    for (int t = 0; t < TT; t++) { accP0[t] = 0.f; accP1[t] = 0.f; }

#pragma unroll 2
    for (int q = 0; q < FP / 4; q++) {               // 16 iters
        float4 w = wf4[q];
        float4 v = vf4[q];
#pragma unroll
        for (int t = 0; t < TT; t++) {
            float4 u = uhf4[t * (FP / 4) + q];
            float a0 = accP0[t], a1 = accP1[t];
            a0 = pade_acc(w.x + u.x, v.x, a0);
            a1 = pade_acc(w.y + u.y, v.y, a1);
            a0 = pade_acc(w.z + u.z, v.z, a0);
            a1 = pade_acc(w.w + u.w, v.w, a1);
            accP0[t] = a0; accP1[t] = a1;
        }
    }

    // ---- MUFU path (f16x2 tanh), features 64..127 ----
    __half2 zero = __float2half2_rn(0.f);
    __half2 accA[TT], accB[TT];
#pragma unroll
    for (int t = 0; t < TT; t++) { accA[t] = zero; accB[t] = zero; }

#pragma unroll 2
    for (int q8 = 0; q8 < FM / 8; q8++) {            // 8 iters, 8 halves each
        uint4 wv = wh4[q8];
        __half2 w0 = u2h(wv.x), w1 = u2h(wv.y), w2 = u2h(wv.z), w3 = u2h(wv.w);
        uint4 vv = vh4[q8];
        __half2 v0 = u2h(vv.x), v1 = u2h(vv.y), v2 = u2h(vv.z), v3 = u2h(vv.w);
#pragma unroll
        for (int t = 0; t < TT; t++) {
            uint4 uv = uhh4[t * (FM / 8) + q8];
            __half2 x0 = __hadd2(w0, u2h(uv.x));
            __half2 x1 = __hadd2(w1, u2h(uv.y));
            __half2 x2 = __hadd2(w2, u2h(uv.z));
            __half2 x3 = __hadd2(w3, u2h(uv.w));
            accA[t] = __hfma2(tanh2_f16(x0), v0, accA[t]);
            accB[t] = __hfma2(tanh2_f16(x1), v1, accB[t]);
            accA[t] = __hfma2(tanh2_f16(x2), v2, accA[t]);
            accB[t] = __hfma2(tanh2_f16(x3), v3, accB[t]);
        }
    }

    size_t base = ((size_t)(b * TD + t0)) * TE + s;
#pragma unroll
    for (int t = 0; t < TT; t++) {
        float2 fa = __half22float2(accA[t]);
        float2 fb = __half22float2(accB[t]);
        g_scores[base + (size_t)t * TE] =
            (accP0[t] + accP1[t]) + ((fa.x + fa.y) + (fb.x + fb.y));
    }
}

// ================= Softmax + context kernel =================
// grid 256 = (b, t-tile of 4), 512 threads.
__global__ __launch_bounds__(512) void smctx_kernel(
    const float* __restrict__ enc,
    float* __restrict__ c_out,   // [B,TD,HE]
    float* __restrict__ e_out)   // [B,TD,TE]
{
    __shared__ float s_scores[TT * TE];          // 8 KB
    __shared__ float s_ctx[4][TT * HE];          // 8 KB

    int blk = blockIdx.x;
    int b  = blk / (TD / TT);
    int t0 = (blk % (TD / TT)) * TT;
    int tid  = threadIdx.x;                      // 0..511
    int warp = tid >> 5;
    int lane = tid & 31;

#pragma unroll
    for (int t = 0; t < TT; t++)
        s_scores[t * TE + tid] = g_scores[((size_t)(b * TD + t0 + t)) * TE + tid];
    __syncthreads();

    if (warp < TT) {
        int t = warp;
        float* sc = s_scores + t * TE;
        float m = -1e30f;
        for (int s = lane; s < TE; s += 32) m = fmaxf(m, sc[s]);
#pragma unroll
        for (int o = 16; o > 0; o >>= 1)
            m = fmaxf(m, __shfl_xor_sync(0xFFFFFFFFu, m, o));
        float sum = 0.f;
        for (int s = lane; s < TE; s += 32) {
            float ex = __expf(sc[s] - m);
            sc[s] = ex;
            sum += ex;
        }
#pragma unroll
        for (int o = 16; o > 0; o >>= 1)
            sum += __shfl_xor_sync(0xFFFFFFFFu, sum, o);
        float inv = 1.0f / sum;
        float* eo = e_out + ((size_t)(b * TD + t0 + t)) * TE;
        for (int s = lane; s < TE; s += 32) {
            float w = sc[s] * inv;
            sc[s] = w;
            eo[s] = w;
        }
    }
    __syncthreads();

    {
        int g  = tid >> 7;              // 0..3
        int ee = tid & 127;
        const float* encb = enc + (size_t)b * TE * HE;
        float a0 = 0.f, a1 = 0.f, a2 = 0.f, a3 = 0.f;
        int sbeg = g * (TE / 4);
#pragma unroll 2
        for (int s = sbeg; s < sbeg + TE / 4; s += 4) {
            float4 w0 = *reinterpret_cast<const float4*>(&s_scores[0 * TE + s]);
            float4 w1 = *reinterpret_cast<const float4*>(&s_scores[1 * TE + s]);
            float4 w2 = *reinterpret_cast<const float4*>(&s_scores[2 * TE + s]);
            float4 w3 = *reinterpret_cast<const float4*>(&s_scores[3 * TE + s]);
            float x0 = encb[(size_t)(s + 0) * HE + ee];
            float x1 = encb[(size_t)(s + 1) * HE + ee];
            float x2 = encb[(size_t)(s + 2) * HE + ee];
            float x3 = encb[(size_t)(s + 3) * HE + ee];
            a0 = fmaf(w0.x, x0, fmaf(w0.y, x1, fmaf(w0.z, x2, fmaf(w0.w, x3, a0))));
            a1 = fmaf(w1.x, x0, fmaf(w1.y, x1, fmaf(w1.z, x2, fmaf(w1.w, x3, a1))));
            a2 = fmaf(w2.x, x0, fmaf(w2.y, x1, fmaf(w2.z, x2, fmaf(w2.w, x3, a2))));
            a3 = fmaf(w3.x, x0, fmaf(w3.y, x1, fmaf(w3.z, x2, fmaf(w3.w, x3, a3))));
        }
        s_ctx[g][0 * HE + ee] = a0;
        s_ctx[g][1 * HE + ee] = a1;
        s_ctx[g][2 * HE + ee] = a2;
        s_ctx[g][3 * HE + ee] = a3;
    }
    __syncthreads();

    {
        float r = s_ctx[0][tid] + s_ctx[1][tid] + s_ctx[2][tid] + s_ctx[3][tid];
        int tt = tid >> 7;
        int ee = tid & 127;
        c_out[((size_t)(b * TD + t0 + tt)) * HE + ee] = r;
    }
}

extern "C" void kernel_launch(void* const* d_in, const int* in_sizes, int n_in,
                              void* d_out, int out_size) {
    const float* enc = (const float*)d_in[0];   // [B,TE,HE]
    const float* dec = (const float*)d_in[1];   // [B,TD,HD]
    const float* Wa  = (const float*)d_in[2];   // [HE,HE]
    const float* Ua  = (const float*)d_in[3];   // [HD,HE]
    const float* Va  = (const float*)d_in[4];   // [HE,1]

    float* out   = (float*)d_out;
    float* c_out = out;                          // [B,TD,HE]
    float* e_out = out + (size_t)BB * TD * HE;   // [B,TD,TE]

    prep_kernel<<<512, 128>>>(dec, Ua, enc, Wa);
    score_kernel<<<BB * 4 * 64, 128>>>(Va);
    smctx_kernel<<<BB * (TD / TT), 512>>>(enc, c_out, e_out);
}

// round 11
// speedup vs baseline: 1.0790x; 1.0790x over previous
#include <cuda_runtime.h>
#include <cuda_bf16.h>
#include <cstdint>

#define BB 4
#define TE 512
#define TD 256
#define HE 128
#define HD 256
#define TT 4

// ---- scratch (device globals; no allocation allowed) ----
__device__ float g_TWs[BB * TE * HE];       // tanh(enc @ W_a)  [B,TE,HE]
__device__ float g_TUh[BB * TD * HE];       // tanh(dec @ U_a)  [B,TD,HE]
__device__ float g_scores[BB * TD * TE];    // raw scores [B,TD,TE]

__device__ __forceinline__ float fast_tanh(float x) {
    float y;
    asm("tanh.approx.f32 %0, %1;" : "=f"(y) : "f"(x));
    return y;
}
__device__ __forceinline__ float fast_rcp(float x) {
    float r;
    asm("rcp.approx.ftz.f32 %0, %1;" : "=f"(r) : "f"(x));
    return r;
}

// ================= Prep kernel: TUh = tanh(dec@U), TWs = tanh(enc@W) ========
__global__ __launch_bounds__(128) void prep_kernel(
    const float* __restrict__ dec, const float* __restrict__ U,
    const float* __restrict__ enc, const float* __restrict__ W)
{
    __shared__ float sbuf[1024];                 // 4 KB
    int tid = threadIdx.x;

    if (blockIdx.x < 256) {
        // ---- Uh: rows = B*TD, 4 per block ----
        int blk = blockIdx.x;
        int b  = blk >> 6;
        int t0 = (blk & 63) * 4;
        const float4* drow = reinterpret_cast<const float4*>(dec + ((size_t)b * TD + t0) * HD);
        float4* sb4 = reinterpret_cast<float4*>(sbuf);
#pragma unroll
        for (int i = 0; i < 2; i++) sb4[tid + 128 * i] = drow[tid + 128 * i];
        __syncthreads();

        float a0 = 0.f, a1 = 0.f, a2 = 0.f, a3 = 0.f;
#pragma unroll 4
        for (int d = 0; d < HD; d += 4) {
            float u0 = U[(d + 0) * HE + tid];
            float u1 = U[(d + 1) * HE + tid];
            float u2 = U[(d + 2) * HE + tid];
            float u3 = U[(d + 3) * HE + tid];
#pragma unroll
            for (int j = 0; j < 4; j++) {
                float uj = (j == 0) ? u0 : (j == 1) ? u1 : (j == 2) ? u2 : u3;
                a0 = fmaf(sbuf[0 * HD + d + j], uj, a0);
                a1 = fmaf(sbuf[1 * HD + d + j], uj, a1);
                a2 = fmaf(sbuf[2 * HD + d + j], uj, a2);
                a3 = fmaf(sbuf[3 * HD + d + j], uj, a3);
            }
        }
        size_t base = ((size_t)(b * TD + t0)) * HE + tid;
        g_TUh[base + 0 * HE] = fast_tanh(a0);
        g_TUh[base + 1 * HE] = fast_tanh(a1);
        g_TUh[base + 2 * HE] = fast_tanh(a2);
        g_TUh[base + 3 * HE] = fast_tanh(a3);
    } else {
        // ---- Ws: rows = B*TE, 8 per block ----
        int blk = blockIdx.x - 256;
        int b  = blk >> 6;
        int s0 = (blk & 63) * 8;
        const float4* erow = reinterpret_cast<const float4*>(enc + ((size_t)b * TE + s0) * HE);
        float4* sb4 = reinterpret_cast<float4*>(sbuf);
#pragma unroll
        for (int i = 0; i < 2; i++) sb4[tid + 128 * i] = erow[tid + 128 * i];
        __syncthreads();

        float acc[8];
#pragma unroll
        for (int r = 0; r < 8; r++) acc[r] = 0.f;
#pragma unroll 2
        for (int k = 0; k < HE; k += 4) {
            float w0 = W[(k + 0) * HE + tid];
            float w1 = W[(k + 1) * HE + tid];
            float w2 = W[(k + 2) * HE + tid];
            float w3 = W[(k + 3) * HE + tid];
#pragma unroll
            for (int r = 0; r < 8; r++) {
                float aa = acc[r];
                aa = fmaf(sbuf[r * HE + k + 0], w0, aa);
                aa = fmaf(sbuf[r * HE + k + 1], w1, aa);
                aa = fmaf(sbuf[r * HE + k + 2], w2, aa);
                aa = fmaf(sbuf[r * HE + k + 3], w3, aa);
                acc[r] = aa;
            }
        }
        size_t base = ((size_t)(b * TE + s0)) * HE + tid;
#pragma unroll
        for (int r = 0; r < 8; r++) g_TWs[base + (size_t)r * HE] = fast_tanh(acc[r]);
    }
}

// ================= Score kernel: tanh-addition identity ====================
// tanh(ws + uh) = (ta + tb) / (1 + ta*tb), ta/tb precomputed by prep.
// Per feature: FADD + FFMA + RCP + FMUL + FFMA  (4 fma-pipe + 1 MUFU rt8).
// 1024 CTAs: blk = ((b*4 + chunk)*64 + ttile); 128 threads, thread = one s.
__global__ __launch_bounds__(128) void score_kernel(const float* __restrict__ Va)
{
    __shared__ float s_tu[TT * HE];              // 2 KB
    __shared__ float s_v[HE];                    // 0.5 KB

    int blk   = blockIdx.x;
    int ttile = blk & 63;
    int chunk = (blk >> 6) & 3;
    int b     = blk >> 8;
    int t0    = ttile * TT;
    int tid   = threadIdx.x;                     // 0..127
    int s     = chunk * 128 + tid;

#pragma unroll
    for (int i = 0; i < TT; i++)
        s_tu[i * HE + tid] = g_TUh[((size_t)(b * TD + t0 + i)) * HE + tid];
    s_v[tid] = Va[tid];
    __syncthreads();

    const float4* tu4  = reinterpret_cast<const float4*>(s_tu);
    const float4* v4p  = reinterpret_cast<const float4*>(s_v);
    const float4* wrow = reinterpret_cast<const float4*>(
        g_TWs + ((size_t)b * TE + s) * HE);

    float acc[TT];
#pragma unroll
    for (int t = 0; t < TT; t++) acc[t] = 0.f;

#pragma unroll 8
    for (int q = 0; q < HE / 4; q++) {
        float4 w = wrow[q];
        float4 v = v4p[q];
#pragma unroll
        for (int t = 0; t < TT; t++) {
            float4 u = tu4[t * (HE / 4) + q];
            float a = acc[t];
            a = fmaf(v.x * (w.x + u.x), fast_rcp(fmaf(w.x, u.x, 1.0f)), a);
            a = fmaf(v.y * (w.y + u.y), fast_rcp(fmaf(w.y, u.y, 1.0f)), a);
            a = fmaf(v.z * (w.z + u.z), fast_rcp(fmaf(w.z, u.z, 1.0f)), a);
            a = fmaf(v.w * (w.w + u.w), fast_rcp(fmaf(w.w, u.w, 1.0f)), a);
            acc[t] = a;
        }
    }

    size_t base = ((size_t)(b * TD + t0)) * TE + s;
#pragma unroll
    for (int t = 0; t < TT; t++)
        g_scores[base + (size_t)t * TE] = acc[t];
}

// ================= Softmax + context kernel =================
// grid 256 = (b, t-tile of 4), 512 threads.
__global__ __launch_bounds__(512) void smctx_kernel(
    const float* __restrict__ enc,
    float* __restrict__ c_out,   // [B,TD,HE]
    float* __restrict__ e_out)   // [B,TD,TE]
{
    __shared__ float s_scores[TT * TE];          // 8 KB
    __shared__ float s_ctx[4][TT * HE];          // 8 KB

    int blk = blockIdx.x;
    int b  = blk / (TD / TT);
    int t0 = (blk % (TD / TT)) * TT;
    int tid  = threadIdx.x;                      // 0..511
    int warp = tid >> 5;
    int lane = tid & 31;

#pragma unroll
    for (int t = 0; t < TT; t++)
        s_scores[t * TE + tid] = g_scores[((size_t)(b * TD + t0 + t)) * TE + tid];
    __syncthreads();

    if (warp < TT) {
        int t = warp;
        float* sc = s_scores + t * TE;
        float m = -1e30f;
        for (int s = lane; s < TE; s += 32) m = fmaxf(m, sc[s]);
#pragma unroll
        for (int o = 16; o > 0; o >>= 1)
            m = fmaxf(m, __shfl_xor_sync(0xFFFFFFFFu, m, o));
        float sum = 0.f;
        for (int s = lane; s < TE; s += 32) {
            float ex = __expf(sc[s] - m);
            sc[s] = ex;
            sum += ex;
        }
#pragma unroll
        for (int o = 16; o > 0; o >>= 1)
            sum += __shfl_xor_sync(0xFFFFFFFFu, sum, o);
        float inv = 1.0f / sum;
        float* eo = e_out + ((size_t)(b * TD + t0 + t)) * TE;
        for (int s = lane; s < TE; s += 32) {
            float w = sc[s] * inv;
            sc[s] = w;
            eo[s] = w;
        }
    }
    __syncthreads();

    {
        int g  = tid >> 7;              // 0..3
        int ee = tid & 127;
        const float* encb = enc + (size_t)b * TE * HE;
        float a0 = 0.f, a1 = 0.f, a2 = 0.f, a3 = 0.f;
        int sbeg = g * (TE / 4);
#pragma unroll 2
        for (int s = sbeg; s < sbeg + TE / 4; s += 4) {
            float4 w0 = *reinterpret_cast<const float4*>(&s_scores[0 * TE + s]);
            float4 w1 = *reinterpret_cast<const float4*>(&s_scores[1 * TE + s]);
            float4 w2 = *reinterpret_cast<const float4*>(&s_scores[2 * TE + s]);
            float4 w3 = *reinterpret_cast<const float4*>(&s_scores[3 * TE + s]);
            float x0 = encb[(size_t)(s + 0) * HE + ee];
            float x1 = encb[(size_t)(s + 1) * HE + ee];
            float x2 = encb[(size_t)(s + 2) * HE + ee];
            float x3 = encb[(size_t)(s + 3) * HE + ee];
            a0 = fmaf(w0.x, x0, fmaf(w0.y, x1, fmaf(w0.z, x2, fmaf(w0.w, x3, a0))));
            a1 = fmaf(w1.x, x0, fmaf(w1.y, x1, fmaf(w1.z, x2, fmaf(w1.w, x3, a1))));
            a2 = fmaf(w2.x, x0, fmaf(w2.y, x1, fmaf(w2.z, x2, fmaf(w2.w, x3, a2))));
            a3 = fmaf(w3.x, x0, fmaf(w3.y, x1, fmaf(w3.z, x2, fmaf(w3.w, x3, a3))));
        }
        s_ctx[g][0 * HE + ee] = a0;
        s_ctx[g][1 * HE + ee] = a1;
        s_ctx[g][2 * HE + ee] = a2;
        s_ctx[g][3 * HE + ee] = a3;
    }
    __syncthreads();

    {
        float r = s_ctx[0][tid] + s_ctx[1][tid] + s_ctx[2][tid] + s_ctx[3][tid];
        int tt = tid >> 7;
        int ee = tid & 127;
        c_out[((size_t)(b * TD + t0 + tt)) * HE + ee] = r;
    }
}

extern "C" void kernel_launch(void* const* d_in, const int* in_sizes, int n_in,
                              void* d_out, int out_size) {
    const float* enc = (const float*)d_in[0];   // [B,TE,HE]
    const float* dec = (const float*)d_in[1];   // [B,TD,HD]
    const float* Wa  = (const float*)d_in[2];   // [HE,HE]
    const float* Ua  = (const float*)d_in[3];   // [HD,HE]
    const float* Va  = (const float*)d_in[4];   // [HE,1]

    float* out   = (float*)d_out;
    float* c_out = out;                          // [B,TD,HE]
    float* e_out = out + (size_t)BB * TD * HE;   // [B,TD,TE]

    prep_kernel<<<512, 128>>>(dec, Ua, enc, Wa);
    score_kernel<<<BB * 4 * 64, 128>>>(Va);
    smctx_kernel<<<BB * (TD / TT), 512>>>(enc, c_out, e_out);
}